// round 12
// baseline (speedup 1.0000x reference)
#include <cuda_runtime.h>
#include <cuda_bf16.h>
#include <cuda_pipeline.h>
#include <math.h>

#define BB   64
#define LL   65536
#define NW   2047
#define WPB  128
#define BPB  16
#define SPAN_MAX 4128
#define HID  512
#define DM   256
#define SD   321

#define GRID2 128
// dynamic smem layout (bytes)
#define OFF_W1 0
#define OFF_W2 49152
#define OFF_W3 114688
#define OFF_A  147456
#define OFF_MISC 152576
#define SMEM2  154624

// ---------------- scratch (__device__ globals; no allocation allowed) -------
__device__ unsigned int g_hist_parts[BB * BPB * 256];
__device__ float g_went[BB * NW];
__device__ float g_feats[BB * SD];
__device__ float g_z1p[4][BB * HID];
__device__ float g_z2p[4][BB * HID];
__device__ float g_outp[8][BB * DM];
__device__ unsigned int g_cnt[4][8];

// ---------------- Kernel A: windowed entropies via half-window hists --------
__global__ void __launch_bounds__(256) win_kernel(const int* __restrict__ x) {
    const int b    = blockIdx.y;
    const int blk  = blockIdx.x;
    const int tid  = threadIdx.x;
    const int lane = tid & 31;
    const int warp = tid >> 5;

    if (blk == 0 && b == 0 && tid < 32) ((unsigned int*)g_cnt)[tid] = 0u;

    const int wstart = blk * WPB;
    const int wcount = min(WPB, NW - wstart);        // 128 (or 127 last)
    const int nh     = wcount + 1;                    // half-hists needed
    const int span   = nh * 32;                       // 4128 or 4096
    const long base  = (long)b * LL + (long)blk * (WPB * 32);

    __shared__ __align__(16) unsigned char s_x[SPAN_MAX + 32];
    __shared__ unsigned int  s_half[129][64];  // packed u8 counts per half-window
    __shared__ unsigned int  s_part[256];
    __shared__ float         s_lut[65];

    if (tid < 256) s_part[tid] = 0u;
    if (tid <= 64) {
        if (tid == 0) s_lut[0] = 0.0f;
        else {
            float p = (float)tid * (1.0f / 64.0f);
            float t = -(p * log2f(p + 1e-10f));
            s_lut[tid] = t / (float)tid;
        }
    }
    {
        const int4* xv = (const int4*)(x + base);
        uchar4* sv = (uchar4*)s_x;
        const int n4 = span >> 2;
        for (int i = tid; i < n4; i += 256) {
            int4 v = xv[i];
            sv[i] = make_uchar4((unsigned char)min(max(v.x, 0), 255),
                                (unsigned char)min(max(v.y, 0), 255),
                                (unsigned char)min(max(v.z, 0), 255),
                                (unsigned char)min(max(v.w, 0), 255));
        }
    }
    __syncthreads();

    // ---- build half-window hists: each byte inserted exactly once ----
    for (int j = warp; j < nh; j += 8) {
        unsigned int* h = s_half[j];
        h[lane]      = 0u;
        h[lane + 32] = 0u;
        __syncwarp();
        const int v = s_x[j * 32 + lane];
        atomicAdd(&h[v >> 2], 1u << ((v & 3) << 3));
    }
    __syncthreads();

    // ---- windows: counts from the two half-hists, no atomics ----
    for (int wi = warp; wi < wcount; wi += 8) {
        const int off = wi * 32;
        const int va = s_x[off + lane];
        const int vb = s_x[off + 32 + lane];
        const int sa = (va & 3) << 3, wa = va >> 2;
        const int sb = (vb & 3) << 3, wb = vb >> 2;
        const unsigned ca = ((s_half[wi][wa] >> sa) & 0xFFu) + ((s_half[wi + 1][wa] >> sa) & 0xFFu);
        const unsigned cb = ((s_half[wi][wb] >> sb) & 0xFFu) + ((s_half[wi + 1][wb] >> sb) & 0xFFu);
        float h = s_lut[ca] + s_lut[cb];
        #pragma unroll
        for (int o = 16; o; o >>= 1) h += __shfl_xor_sync(0xffffffffu, h, o);
        if (lane == 0) g_went[b * NW + wstart + wi] = h;
    }
    __syncthreads();

    // ---- global partial = sum of owned half-hists (local 0..127) ----
    {
        const int w = tid & 63;          // word index (4 bins)
        const int q = tid >> 6;          // quarter of j-range
        unsigned int lo = 0u, hi = 0u;
        const int j0 = q * 32, j1 = j0 + 32;
        for (int j = j0; j < j1; j++) {
            const unsigned wd = s_half[j][w];
            lo += wd & 0x00FF00FFu;
            hi += (wd >> 8) & 0x00FF00FFu;
        }
        atomicAdd(&s_part[w * 4 + 0], lo & 0xFFFFu);
        atomicAdd(&s_part[w * 4 + 2], lo >> 16);
        atomicAdd(&s_part[w * 4 + 1], hi & 0xFFFFu);
        atomicAdd(&s_part[w * 4 + 3], hi >> 16);
    }
    __syncthreads();
    if (tid < 256) g_hist_parts[(b * BPB + blk) * 256 + tid] = s_part[tid];
}

// ---------------- dataflow sync helpers --------------------------------------
__device__ __forceinline__ void publish(unsigned int* c) {
    __syncthreads();
    __threadfence();
    if (threadIdx.x == 0) atomicAdd(c, 1u);
}
__device__ __forceinline__ void waitc(unsigned int* c, unsigned int tgt) {
    __syncthreads();
    if (threadIdx.x == 0) {
        volatile unsigned int* p = c;
        while (*p < tgt) {}
        __threadfence();
    }
    __syncthreads();
}

template <int MODE>
__device__ __forceinline__ void job_decode(int job, int& ct, int& rg, int& ks) {
    if (MODE == 3) { ct = job & 1; rg = (job >> 1) & 7; ks = job >> 4; }
    else           { ct = job & 3; rg = (job >> 2) & 7; ks = job >> 5; }
}

template <int MODE>
__device__ __forceinline__ void prefetch_w(const float* __restrict__ W, char* smem) {
    constexpr int CH = (MODE == 1) ? 96 : ((MODE == 2) ? 128 : 64);
    constexpr int N  = (MODE == 3) ? DM : HID;
    constexpr int K  = (MODE == 1) ? SD : HID;
    constexpr int NCHUNK = CH * 32;

    char* dst_base = smem + ((MODE == 1) ? OFF_W1 : ((MODE == 2) ? OFF_W2 : OFF_W3));
    int ct, rg, ks;
    job_decode<MODE>(blockIdx.x, ct, rg, ks);
    const int c0 = ct * 128, k0 = ks * CH;

    const int tid = threadIdx.x;
    #pragma unroll
    for (int i = 0; i < NCHUNK / 256; i++) {
        const int c  = tid + i * 256;
        const int kr = c >> 5;
        const int cb = (c & 31) * 16;
        int ksrc = k0 + kr;
        if (MODE == 1 && ksrc >= K) ksrc = K - 1;   // clamp; A is zero there
        const char* src = (const char*)W + (long)ksrc * (N * 4) + (long)c0 * 4 + cb;
        __pipeline_memcpy_async(dst_base + c * 16, src, 16);
    }
    __pipeline_commit();
}

// GEMM stage with dataflow waits. (see R11 comments)
template <int MODE>
__device__ void mlp_gemm(char* smem,
                         const float* __restrict__ bias,
                         const float* __restrict__ gam,
                         const float* __restrict__ bet) {
    constexpr int CH = (MODE == 1) ? 96 : ((MODE == 2) ? 128 : 64);
    constexpr int N  = (MODE == 3) ? DM : HID;
    constexpr int K  = (MODE == 1) ? SD : HID;

    int ct, rg, ks;
    job_decode<MODE>(blockIdx.x, ct, rg, ks);
    const int c0 = ct * 128, r0 = rg * 8, k0 = ks * CH;

    if (MODE == 1) waitc(&g_cnt[0][rg], 8);
    else           waitc(&g_cnt[MODE - 1][rg], 16);

    float* s_w = (float*)(smem + ((MODE == 1) ? OFF_W1 : ((MODE == 2) ? OFF_W2 : OFF_W3)));
    float* s_a = (float*)(smem + OFF_A);     // [CH][10]

    const int tid  = threadIdx.x;
    const int lane = tid & 31;
    const int w    = tid >> 5;

    __pipeline_wait_prior(3 - MODE);

    if (MODE == 1) {
        for (int idx = tid; idx < 8 * CH; idx += 256) {
            const int r = idx / CH, k = idx - r * CH;
            float v = 0.f;
            if ((k0 + k) < K) v = g_feats[(r0 + r) * SD + k0 + k];
            s_a[k * 10 + r] = v;
        }
    } else {
        const float* P = (MODE == 2) ? &g_z1p[0][0] : &g_z2p[0][0];
        const int r = r0 + w;
        float zv[16];
        float sum = 0.f;
        #pragma unroll
        for (int i = 0; i < 16; i++) {
            const int k = lane + 32 * i;
            float z = bias[k];
            #pragma unroll
            for (int s = 0; s < 4; s++) z += P[(long)s * (BB * HID) + r * HID + k];
            zv[i] = z; sum += z;
        }
        #pragma unroll
        for (int o = 16; o; o >>= 1) sum += __shfl_xor_sync(0xffffffffu, sum, o);
        const float mu = sum * (1.0f / 512.0f);
        float vs = 0.f;
        #pragma unroll
        for (int i = 0; i < 16; i++) { const float d = zv[i] - mu; vs += d * d; }
        #pragma unroll
        for (int o = 16; o; o >>= 1) vs += __shfl_xor_sync(0xffffffffu, vs, o);
        const float rstd = rsqrtf(vs * (1.0f / 512.0f) + 1e-5f);
        #pragma unroll
        for (int j = 0; j < CH / 32; j++) {
            const int i = (k0 >> 5) + j;
            const int k = lane + 32 * i;
            const float hv = (zv[i] - mu) * rstd * gam[k] + bet[k];
            s_a[(k - k0) * 10 + w] = fmaxf(hv, 0.0f);
        }
    }
    __syncthreads();

    const int rp = tid >> 6, cp = tid & 63;
    float a00 = 0.f, a01 = 0.f, a10 = 0.f, a11 = 0.f;
    #pragma unroll 8
    for (int kk = 0; kk < CH; kk++) {
        const float2 wv = *(const float2*)&s_w[kk * 128 + cp * 2];
        const float2 av = *(const float2*)&s_a[kk * 10 + rp * 2];
        a00 = fmaf(av.x, wv.x, a00);
        a01 = fmaf(av.x, wv.y, a01);
        a10 = fmaf(av.y, wv.x, a10);
        a11 = fmaf(av.y, wv.y, a11);
    }

    float* OP = (MODE == 1) ? &g_z1p[0][0] : ((MODE == 2) ? &g_z2p[0][0] : &g_outp[0][0]);
    const long base = (long)ks * (BB * N);
    const int r = r0 + rp * 2, cc = c0 + cp * 2;
    *(float2*)&OP[base + (long)r * N + cc]       = make_float2(a00, a01);
    *(float2*)&OP[base + (long)(r + 1) * N + cc] = make_float2(a10, a11);

    publish(&g_cnt[MODE][rg]);
}

__global__ void __launch_bounds__(256, 1) mlp_fused5(
    const float* __restrict__ W1, const float* __restrict__ b1,
    const float* __restrict__ g1, const float* __restrict__ be1,
    const float* __restrict__ W2, const float* __restrict__ b2,
    const float* __restrict__ g2, const float* __restrict__ be2,
    const float* __restrict__ W3, const float* __restrict__ b3,
    float* __restrict__ out) {
    extern __shared__ __align__(16) char smem[];
    const int job = blockIdx.x;
    const int tid = threadIdx.x;

    prefetch_w<1>(W1, smem);
    prefetch_w<2>(W2, smem);
    prefetch_w<3>(W3, smem);

    // ---- feat: blocks 0-63, one batch row each ----
    if (job < BB) {
        const int b = job;
        unsigned int* s_cnt = (unsigned int*)(smem + OFF_MISC);   // [64]
        float* s_lev  = (float*)(smem + OFF_MISC + 256);          // [64]
        float* s_wred = (float*)(smem + OFF_MISC + 512);          // [8]

        float term = 0.0f;
        {
            unsigned int c = 0;
            #pragma unroll
            for (int p = 0; p < BPB; p++)
                c += g_hist_parts[(b * BPB + p) * 256 + tid];
            float nh = (float)c * (1.0f / 65536.0f);
            g_feats[b * SD + tid] = nh;
            term = -(nh * log2f(nh + 1e-10f));
        }
        if (tid < 64) {
            s_lev[tid] = (tid == 63) ? 8.0f : (float)tid * (8.0f / 63.0f);
            s_cnt[tid] = 0u;
        }
        {
            const int lane = tid & 31, wid = tid >> 5;
            float t = term;
            #pragma unroll
            for (int o = 16; o; o >>= 1) t += __shfl_xor_sync(0xffffffffu, t, o);
            if (lane == 0) s_wred[wid] = t;
            __syncthreads();
            if (tid == 0) {
                float u = 0.f;
                #pragma unroll
                for (int i = 0; i < 8; i++) u += s_wred[i];
                g_feats[b * SD + 256] = u;
            }
        }

        // CDF bucketing: direct index + verify, warp-aggregated atomic
        const int lane = tid & 31;
        for (int i = tid; i < NW; i += 256) {
            const float h = g_went[b * NW + i];
            int j = (int)(h * 7.875f);
            j = min(max(j, 0), 63);
            while (j > 0 && h <= s_lev[j - 1]) j--;
            while (j < 63 && h > s_lev[j]) j++;
            const unsigned m = __match_any_sync(__activemask(), j);
            if ((m & ((1u << lane) - 1u)) == 0u)
                atomicAdd(&s_cnt[j], (unsigned)__popc(m));
        }
        __syncthreads();
        // inclusive scan over 64 buckets (Hillis-Steele)
        #pragma unroll
        for (int o = 1; o < 64; o <<= 1) {
            unsigned v = 0;
            if (tid < 64 && tid >= o) v = s_cnt[tid - o];
            __syncthreads();
            if (tid < 64) s_cnt[tid] += v;
            __syncthreads();
        }
        if (tid < 64)
            g_feats[b * SD + 257 + tid] = (float)s_cnt[tid] / 2047.0f;
        publish(&g_cnt[0][b >> 3]);
    }

    mlp_gemm<1>(smem, nullptr, nullptr, nullptr);
    mlp_gemm<2>(smem, b1, g1, be1);
    mlp_gemm<3>(smem, b2, g2, be2);

    // ---- finalize: blocks 0-63, one row each ----
    if (job < BB) {
        waitc(&g_cnt[3][job >> 3], 16);
        const int i = job * DM + tid;
        float v = b3[tid];
        #pragma unroll
        for (int s = 0; s < 8; s++) v += g_outp[s][i];
        out[i] = v;
    }
}

// ---------------- launch ----------------------------------------------------
extern "C" void kernel_launch(void* const* d_in, const int* in_sizes, int n_in,
                              void* d_out, int out_size) {
    const int*   x   = (const int*)d_in[0];
    const float* W1  = (const float*)d_in[1];
    const float* b1  = (const float*)d_in[2];
    const float* g1  = (const float*)d_in[3];
    const float* be1 = (const float*)d_in[4];
    const float* W2  = (const float*)d_in[5];
    const float* b2  = (const float*)d_in[6];
    const float* g2  = (const float*)d_in[7];
    const float* be2 = (const float*)d_in[8];
    const float* W3  = (const float*)d_in[9];
    const float* b3  = (const float*)d_in[10];
    float* out = (float*)d_out;

    cudaFuncSetAttribute(mlp_fused5, cudaFuncAttributeMaxDynamicSharedMemorySize, SMEM2);

    win_kernel<<<dim3(BPB, BB), 256>>>(x);
    mlp_fused5<<<GRID2, 256, SMEM2>>>(W1, b1, g1, be1, W2, b2, g2, be2, W3, b3, out);
}

// round 13
// speedup vs baseline: 1.0520x; 1.0520x over previous
#include <cuda_runtime.h>
#include <cuda_bf16.h>
#include <cuda_pipeline.h>
#include <math.h>

#define BB   64
#define LL   65536
#define NW   2047
#define WPB  128
#define BPB  16
#define SPAN_MAX 4128
#define HID  512
#define DM   256
#define SD   321

#define GRID2 128
// dynamic smem layout (bytes)
#define OFF_W1 0
#define OFF_W2 49152
#define OFF_W3 114688
#define OFF_A  147456
#define OFF_MISC 150528
#define SMEM2  152576

// ---------------- scratch (__device__ globals; no allocation allowed) -------
__device__ unsigned int g_hist_parts[BB * BPB * 256];
__device__ float g_went[BB * NW];
__device__ float g_feats[BB * SD];
__device__ float g_z1p[8][BB * HID];
__device__ float g_z2p[8][BB * HID];
__device__ float g_outp[16][BB * DM];
__device__ unsigned int g_cnt[4][8];

// ---------------- Kernel A: windowed entropies + global hist partials -------
// (R11 version: packed u8 per-warp hists, measured best)
__global__ void __launch_bounds__(256) win_kernel(const int* __restrict__ x) {
    const int b    = blockIdx.y;
    const int blk  = blockIdx.x;
    const int tid  = threadIdx.x;
    const int lane = tid & 31;
    const int warp = tid >> 5;

    if (blk == 0 && b == 0 && tid < 32) ((unsigned int*)g_cnt)[tid] = 0u;

    const int wstart = blk * WPB;
    const int wcount = min(WPB, NW - wstart);
    const int span   = (wcount - 1) * 32 + 64;
    const long base  = (long)b * LL + (long)blk * (WPB * 32);

    __shared__ __align__(16) unsigned char s_x[SPAN_MAX + 32];
    __shared__ unsigned int  s_hist[8][64];
    __shared__ unsigned int  s_part[256];
    __shared__ float         s_lut[65];

    if (tid < 256) s_part[tid] = 0u;
    if (tid <= 64) {
        if (tid == 0) s_lut[0] = 0.0f;
        else {
            float p = (float)tid * (1.0f / 64.0f);
            float t = -(p * log2f(p + 1e-10f));
            s_lut[tid] = t / (float)tid;
        }
    }
    {
        const int4* xv = (const int4*)(x + base);
        uchar4* sv = (uchar4*)s_x;
        const int n4 = span >> 2;
        for (int i = tid; i < n4; i += 256) {
            int4 v = xv[i];
            sv[i] = make_uchar4((unsigned char)min(max(v.x, 0), 255),
                                (unsigned char)min(max(v.y, 0), 255),
                                (unsigned char)min(max(v.z, 0), 255),
                                (unsigned char)min(max(v.w, 0), 255));
        }
    }
    __syncthreads();

    for (int i = tid; i < 4096; i += 256)
        atomicAdd(&s_part[s_x[i]], 1u);

    unsigned int* hist = s_hist[warp];
    for (int wi = warp; wi < wcount; wi += 8) {
        const int off = wi * 32;
        hist[lane]      = 0u;
        hist[lane + 32] = 0u;
        __syncwarp();
        const int va = s_x[off + lane];
        const int vb = s_x[off + 32 + lane];
        atomicAdd(&hist[va >> 2], 1u << ((va & 3) << 3));
        atomicAdd(&hist[vb >> 2], 1u << ((vb & 3) << 3));
        __syncwarp();
        const unsigned ca = (hist[va >> 2] >> ((va & 3) << 3)) & 0xFFu;
        const unsigned cb = (hist[vb >> 2] >> ((vb & 3) << 3)) & 0xFFu;
        float h = s_lut[ca] + s_lut[cb];
        #pragma unroll
        for (int o = 16; o; o >>= 1) h += __shfl_xor_sync(0xffffffffu, h, o);
        if (lane == 0) g_went[b * NW + wstart + wi] = h;
    }

    __syncthreads();
    if (tid < 256) g_hist_parts[(b * BPB + blk) * 256 + tid] = s_part[tid];
}

// ---------------- dataflow sync helpers --------------------------------------
__device__ __forceinline__ void publish(unsigned int* c) {
    __syncthreads();
    __threadfence();
    if (threadIdx.x == 0) atomicAdd(c, 1u);
}
__device__ __forceinline__ void waitc(unsigned int* c, unsigned int tgt) {
    __syncthreads();
    if (threadIdx.x == 0) {
        volatile unsigned int* p = c;
        while (*p < tgt) {}
        __threadfence();
    }
    __syncthreads();
}

// job decode: tiles are 8 rows x 256 cols.
// MODE 1: ct2 rg8 ks8  (CH=48)   MODE 2: ct2 rg8 ks8 (CH=64)
// MODE 3: ct1 rg8 ks16 (CH=32)
template <int MODE>
__device__ __forceinline__ void job_decode(int job, int& ct, int& rg, int& ks) {
    if (MODE == 3) { ct = 0; rg = job & 7; ks = job >> 3; }
    else           { ct = job & 1; rg = (job >> 1) & 7; ks = job >> 4; }
}

template <int MODE>
__device__ __forceinline__ void prefetch_w(const float* __restrict__ W, char* smem) {
    constexpr int CH = (MODE == 1) ? 48 : ((MODE == 2) ? 64 : 32);
    constexpr int N  = (MODE == 3) ? DM : HID;
    constexpr int K  = (MODE == 1) ? SD : HID;
    constexpr int NCHUNK = CH * 64;          // 16B chunks (256 cols = 64 chunks/row)

    char* dst_base = smem + ((MODE == 1) ? OFF_W1 : ((MODE == 2) ? OFF_W2 : OFF_W3));
    int ct, rg, ks;
    job_decode<MODE>(blockIdx.x, ct, rg, ks);
    const int c0 = ct * 256, k0 = ks * CH;

    const int tid = threadIdx.x;
    #pragma unroll
    for (int i = 0; i < NCHUNK / 256; i++) {
        const int c  = tid + i * 256;
        const int kr = c >> 6;               // row within tile
        const int cb = (c & 63) * 16;        // byte offset in row (1024B)
        int ksrc = k0 + kr;
        if (MODE == 1 && ksrc >= K) ksrc = K - 1;   // clamp; A is zero there
        const char* src = (const char*)W + (long)ksrc * (N * 4) + (long)c0 * 4 + cb;
        __pipeline_memcpy_async(dst_base + c * 16, src, 16);
    }
    __pipeline_commit();
}

// GEMM stage: 128 jobs, tile 8r x 256c x CH-k, thread tile 2x4.
// MODE 1: A=g_feats (K=321)           -> g_z1p[8]
// MODE 2: A=relu(LN(sum z1p + b1))    -> g_z2p[8]
// MODE 3: A=relu(LN(sum z2p + b2))    -> g_outp[16]  (N=256)
template <int MODE>
__device__ void mlp_gemm(char* smem,
                         const float* __restrict__ bias,
                         const float* __restrict__ gam,
                         const float* __restrict__ bet) {
    constexpr int CH = (MODE == 1) ? 48 : ((MODE == 2) ? 64 : 32);
    constexpr int N  = (MODE == 3) ? DM : HID;
    constexpr int K  = (MODE == 1) ? SD : HID;

    int ct, rg, ks;
    job_decode<MODE>(blockIdx.x, ct, rg, ks);
    const int c0 = ct * 256, r0 = rg * 8, k0 = ks * CH;

    if (MODE == 1) waitc(&g_cnt[0][rg], 8);
    else           waitc(&g_cnt[MODE - 1][rg], 16);

    float* s_w = (float*)(smem + ((MODE == 1) ? OFF_W1 : ((MODE == 2) ? OFF_W2 : OFF_W3)));
    float* s_a = (float*)(smem + OFF_A);     // [CH][10]

    const int tid  = threadIdx.x;
    const int lane = tid & 31;
    const int w    = tid >> 5;

    __pipeline_wait_prior(3 - MODE);

    // ---- stage A ----
    if (MODE == 1) {
        for (int idx = tid; idx < 8 * CH; idx += 256) {
            const int r = idx / CH, k = idx - r * CH;
            float v = 0.f;
            if ((k0 + k) < K) v = g_feats[(r0 + r) * SD + k0 + k];
            s_a[k * 10 + r] = v;
        }
    } else {
        // reduce 8 partials + bias + LN + relu; warp w owns row r0+w
        const float* P = (MODE == 2) ? &g_z1p[0][0] : &g_z2p[0][0];
        const int r = r0 + w;
        float zv[16];
        float sum = 0.f;
        #pragma unroll
        for (int i = 0; i < 16; i++) {
            const int k = lane + 32 * i;
            float z = bias[k];
            #pragma unroll
            for (int s = 0; s < 8; s++) z += P[(long)s * (BB * HID) + r * HID + k];
            zv[i] = z; sum += z;
        }
        #pragma unroll
        for (int o = 16; o; o >>= 1) sum += __shfl_xor_sync(0xffffffffu, sum, o);
        const float mu = sum * (1.0f / 512.0f);
        float vs = 0.f;
        #pragma unroll
        for (int i = 0; i < 16; i++) { const float d = zv[i] - mu; vs += d * d; }
        #pragma unroll
        for (int o = 16; o; o >>= 1) vs += __shfl_xor_sync(0xffffffffu, vs, o);
        const float rstd = rsqrtf(vs * (1.0f / 512.0f) + 1e-5f);
        #pragma unroll
        for (int j = 0; j < CH / 32; j++) {
            const int i = (k0 >> 5) + j;
            const int k = lane + 32 * i;
            const float hv = (zv[i] - mu) * rstd * gam[k] + bet[k];
            s_a[(k - k0) * 10 + w] = fmaxf(hv, 0.0f);
        }
    }
    __syncthreads();

    // ---- compute: 2 rows x 4 cols per thread ----
    const int rp = tid >> 6;          // 0..3 -> rows rp*2, rp*2+1
    const int cp = tid & 63;          // 0..63 -> cols cp*4..cp*4+3
    float a0x = 0.f, a0y = 0.f, a0z = 0.f, a0w = 0.f;
    float a1x = 0.f, a1y = 0.f, a1z = 0.f, a1w = 0.f;
    #pragma unroll 8
    for (int kk = 0; kk < CH; kk++) {
        const float4 wv = *(const float4*)&s_w[kk * 256 + cp * 4];
        const float2 av = *(const float2*)&s_a[kk * 10 + rp * 2];
        a0x = fmaf(av.x, wv.x, a0x);
        a0y = fmaf(av.x, wv.y, a0y);
        a0z = fmaf(av.x, wv.z, a0z);
        a0w = fmaf(av.x, wv.w, a0w);
        a1x = fmaf(av.y, wv.x, a1x);
        a1y = fmaf(av.y, wv.y, a1y);
        a1z = fmaf(av.y, wv.z, a1z);
        a1w = fmaf(av.y, wv.w, a1w);
    }

    float* OP = (MODE == 1) ? &g_z1p[0][0] : ((MODE == 2) ? &g_z2p[0][0] : &g_outp[0][0]);
    const long base = (long)ks * (BB * N);
    const int r = r0 + rp * 2, cc = c0 + cp * 4;
    *(float4*)&OP[base + (long)r * N + cc]       = make_float4(a0x, a0y, a0z, a0w);
    *(float4*)&OP[base + (long)(r + 1) * N + cc] = make_float4(a1x, a1y, a1z, a1w);

    publish(&g_cnt[MODE][rg]);
}

__global__ void __launch_bounds__(256, 1) mlp_fused6(
    const float* __restrict__ W1, const float* __restrict__ b1,
    const float* __restrict__ g1, const float* __restrict__ be1,
    const float* __restrict__ W2, const float* __restrict__ b2,
    const float* __restrict__ g2, const float* __restrict__ be2,
    const float* __restrict__ W3, const float* __restrict__ b3,
    float* __restrict__ out) {
    extern __shared__ __align__(16) char smem[];
    const int job = blockIdx.x;
    const int tid = threadIdx.x;

    prefetch_w<1>(W1, smem);
    prefetch_w<2>(W2, smem);
    prefetch_w<3>(W3, smem);

    // ---- feat: blocks 0-63, one batch row each ----
    if (job < BB) {
        const int b = job;
        unsigned int* s_cnt = (unsigned int*)(smem + OFF_MISC);   // [64]
        float* s_lev  = (float*)(smem + OFF_MISC + 256);          // [64]
        float* s_wred = (float*)(smem + OFF_MISC + 512);          // [8]

        float term = 0.0f;
        {
            unsigned int c = 0;
            #pragma unroll
            for (int p = 0; p < BPB; p++)
                c += g_hist_parts[(b * BPB + p) * 256 + tid];
            float nh = (float)c * (1.0f / 65536.0f);
            g_feats[b * SD + tid] = nh;
            term = -(nh * log2f(nh + 1e-10f));
        }
        if (tid < 64) {
            s_lev[tid] = (tid == 63) ? 8.0f : (float)tid * (8.0f / 63.0f);
            s_cnt[tid] = 0u;
        }
        {
            const int lane = tid & 31, wid = tid >> 5;
            float t = term;
            #pragma unroll
            for (int o = 16; o; o >>= 1) t += __shfl_xor_sync(0xffffffffu, t, o);
            if (lane == 0) s_wred[wid] = t;
            __syncthreads();
            if (tid == 0) {
                float u = 0.f;
                #pragma unroll
                for (int i = 0; i < 8; i++) u += s_wred[i];
                g_feats[b * SD + 256] = u;
            }
        }

        const int lane = tid & 31;
        for (int i = tid; i < NW; i += 256) {
            const float h = g_went[b * NW + i];
            int j = (int)(h * 7.875f);
            j = min(max(j, 0), 63);
            while (j > 0 && h <= s_lev[j - 1]) j--;
            while (j < 63 && h > s_lev[j]) j++;
            const unsigned m = __match_any_sync(__activemask(), j);
            if ((m & ((1u << lane) - 1u)) == 0u)
                atomicAdd(&s_cnt[j], (unsigned)__popc(m));
        }
        __syncthreads();
        #pragma unroll
        for (int o = 1; o < 64; o <<= 1) {
            unsigned v = 0;
            if (tid < 64 && tid >= o) v = s_cnt[tid - o];
            __syncthreads();
            if (tid < 64) s_cnt[tid] += v;
            __syncthreads();
        }
        if (tid < 64)
            g_feats[b * SD + 257 + tid] = (float)s_cnt[tid] / 2047.0f;
        publish(&g_cnt[0][b >> 3]);
    }

    mlp_gemm<1>(smem, nullptr, nullptr, nullptr);
    mlp_gemm<2>(smem, b1, g1, be1);
    mlp_gemm<3>(smem, b2, g2, be2);

    // ---- finalize: blocks 0-63, one row each ----
    if (job < BB) {
        waitc(&g_cnt[3][job >> 3], 16);
        const int i = job * DM + tid;
        float v = b3[tid];
        #pragma unroll
        for (int s = 0; s < 16; s++) v += g_outp[s][i];
        out[i] = v;
    }
}

// ---------------- launch ----------------------------------------------------
extern "C" void kernel_launch(void* const* d_in, const int* in_sizes, int n_in,
                              void* d_out, int out_size) {
    const int*   x   = (const int*)d_in[0];
    const float* W1  = (const float*)d_in[1];
    const float* b1  = (const float*)d_in[2];
    const float* g1  = (const float*)d_in[3];
    const float* be1 = (const float*)d_in[4];
    const float* W2  = (const float*)d_in[5];
    const float* b2  = (const float*)d_in[6];
    const float* g2  = (const float*)d_in[7];
    const float* be2 = (const float*)d_in[8];
    const float* W3  = (const float*)d_in[9];
    const float* b3  = (const float*)d_in[10];
    float* out = (float*)d_out;

    cudaFuncSetAttribute(mlp_fused6, cudaFuncAttributeMaxDynamicSharedMemorySize, SMEM2);

    win_kernel<<<dim3(BPB, BB), 256>>>(x);
    mlp_fused6<<<GRID2, 256, SMEM2>>>(W1, b1, g1, be1, W2, b2, g2, be2, W3, b3, out);
}